// round 2
// baseline (speedup 1.0000x reference)
#include <cuda_runtime.h>
#include <cuda_fp16.h>
#include <cstdint>
#include <cstddef>

// Problem dims
#define HH 32
#define WW 32
#define CC 512
#define CLS 1000
#define RR 64
#define BB 128
#define KTOT 1024   // W*H flattened
#define NKT 64      // k16 tiles
#define NNT 8       // n8 tiles (R=64)
#define NMT 4       // m16 tiles per warp (warp M = 64)

// -------- device scratch (no allocations allowed) --------
__device__ float g_t3[BB * RR];
// V = U2 (x) U1 per rank, pre-laid-out as mma.sync m16n8k16 B-fragments.
// Fragment f = kt*8 + nt; per lane one uint2:
//   .x = half2( V[r][k0],   V[r][k0+1] )
//   .y = half2( V[r][k0+8], V[r][k0+9] )
// with r = nt*8 + lane/4, k0 = kt*16 + (lane%4)*2.
__device__ uint2 g_VfH[NKT * NNT * 32];
__device__ uint2 g_VfL[NKT * NNT * 32];

static __device__ __forceinline__ uint32_t packh2(float a, float b) {
    __half2 h = __floats2half2_rn(a, b);
    return reinterpret_cast<uint32_t&>(h);
}

// ---------------- Kernel 0: precompute V fragments (fp16 hi/lo split) ----------------
__global__ void cp_prep(const float* __restrict__ U1, const float* __restrict__ U2) {
    int gidx = blockIdx.x * 256 + threadIdx.x;   // 0..16383
    int f = gidx >> 5, lane = gidx & 31;
    int kt = f >> 3, nt = f & 7;
    int r  = nt * 8 + (lane >> 2);
    int k0 = kt * 16 + (lane & 3) * 2;

    float v[4];
#pragma unroll
    for (int i = 0; i < 4; ++i) {
        int k = k0 + (i >> 1) * 8 + (i & 1);
        int w = k >> 5, h = k & 31;
        v[i] = U2[w * RR + r] * U1[h * RR + r];
    }
    float hi[4], lo[4];
#pragma unroll
    for (int i = 0; i < 4; ++i) {
        hi[i] = __half2float(__float2half_rn(v[i]));
        lo[i] = v[i] - hi[i];
    }
    g_VfH[f * 32 + lane] = make_uint2(packh2(hi[0], hi[1]), packh2(hi[2], hi[3]));
    g_VfL[f * 32 + lane] = make_uint2(packh2(lo[0], lo[1]), packh2(lo[2], lo[3]));
}

// ---------------- mma.sync helper ----------------
#define MMA16816(d, a0, a1, a2, a3, b0, b1)                                   \
    asm volatile(                                                             \
        "mma.sync.aligned.m16n8k16.row.col.f32.f16.f16.f32 "                  \
        "{%0,%1,%2,%3}, {%4,%5,%6,%7}, {%8,%9}, {%0,%1,%2,%3};"               \
        : "+f"((d)[0]), "+f"((d)[1]), "+f"((d)[2]), "+f"((d)[3])              \
        : "r"(a0), "r"(a1), "r"(a2), "r"(a3), "r"(b0), "r"(b1))

// ---------------- Kernel 1: main fused contraction ----------------
// One CTA per batch b. 8 warps x (M=64, N=64), K=1024.
// Split-fp16: s = xh*Vh + xh*Vl + xl*Vh accumulated in fp32 fragments.
// Epilogue: t3[b,r] = sum_c U3[c,r]*s[c,r].
__global__ void __launch_bounds__(256, 1)
cp_main(const float* __restrict__ x, const float* __restrict__ U3) {
    __shared__ float red[8][RR];
    int tid = threadIdx.x, wid = tid >> 5, lane = tid & 31;
    int g = lane >> 2, tg = lane & 3;
    int b = blockIdx.x;
    int c0 = wid * 64;

    float acc[NMT][NNT][4];
#pragma unroll
    for (int mt = 0; mt < NMT; ++mt)
#pragma unroll
        for (int nt = 0; nt < NNT; ++nt)
#pragma unroll
            for (int i = 0; i < 4; ++i) acc[mt][nt][i] = 0.0f;

    const float* xb = x + ((size_t)b * CC + (size_t)c0) * KTOT;

    for (int kt = 0; kt < NKT; ++kt) {
        // ---- B fragments for this k16 tile (all 8 n-tiles), hi+lo ----
        uint2 bh[NNT], bl[NNT];
        const uint2* pH = g_VfH + (size_t)kt * NNT * 32 + lane;
        const uint2* pL = g_VfL + (size_t)kt * NNT * 32 + lane;
#pragma unroll
        for (int nt = 0; nt < NNT; ++nt) {
            bh[nt] = pH[nt * 32];
            bl[nt] = pL[nt * 32];
        }

        int k0 = kt * 16 + tg * 2;
#pragma unroll
        for (int mt = 0; mt < NMT; ++mt) {
            const float* rowp = xb + (size_t)(mt * 16 + g) * KTOT + k0;
            float2 L0 = *(const float2*)(rowp);
            float2 L1 = *(const float2*)(rowp + 8 * KTOT);
            float2 L2 = *(const float2*)(rowp + 8);
            float2 L3 = *(const float2*)(rowp + 8 * KTOT + 8);

            // fp32 -> fp16 hi/lo split, packed into A fragments
            float h00 = __half2float(__float2half_rn(L0.x));
            float h01 = __half2float(__float2half_rn(L0.y));
            float h10 = __half2float(__float2half_rn(L1.x));
            float h11 = __half2float(__float2half_rn(L1.y));
            float h20 = __half2float(__float2half_rn(L2.x));
            float h21 = __half2float(__float2half_rn(L2.y));
            float h30 = __half2float(__float2half_rn(L3.x));
            float h31 = __half2float(__float2half_rn(L3.y));

            uint32_t ah0 = packh2(h00, h01);
            uint32_t ah1 = packh2(h10, h11);
            uint32_t ah2 = packh2(h20, h21);
            uint32_t ah3 = packh2(h30, h31);
            uint32_t al0 = packh2(L0.x - h00, L0.y - h01);
            uint32_t al1 = packh2(L1.x - h10, L1.y - h11);
            uint32_t al2 = packh2(L2.x - h20, L2.y - h21);
            uint32_t al3 = packh2(L3.x - h30, L3.y - h31);

#pragma unroll
            for (int nt = 0; nt < NNT; ++nt) {
                MMA16816(acc[mt][nt], ah0, ah1, ah2, ah3, bh[nt].x, bh[nt].y);
                MMA16816(acc[mt][nt], ah0, ah1, ah2, ah3, bl[nt].x, bl[nt].y);
                MMA16816(acc[mt][nt], al0, al1, al2, al3, bh[nt].x, bh[nt].y);
            }
        }
    }

    // ---- epilogue: weight by U3[c,r], reduce over c ----
    // D fragment: d0=D[g][r0], d1=D[g][r0+1], d2=D[g+8][r0], d3=D[g+8][r0+1],
    // with r0 = nt*8 + tg*2, rows c = c0 + mt*16 + {g, g+8}.
    float pr0[NNT], pr1[NNT];
#pragma unroll
    for (int nt = 0; nt < NNT; ++nt) { pr0[nt] = 0.0f; pr1[nt] = 0.0f; }

#pragma unroll
    for (int mt = 0; mt < NMT; ++mt) {
        int crow = c0 + mt * 16 + g;
#pragma unroll
        for (int nt = 0; nt < NNT; ++nt) {
            int r0 = nt * 8 + tg * 2;
            float2 uA = *(const float2*)(U3 + (size_t)crow * RR + r0);
            float2 uB = *(const float2*)(U3 + (size_t)(crow + 8) * RR + r0);
            pr0[nt] += acc[mt][nt][0] * uA.x + acc[mt][nt][2] * uB.x;
            pr1[nt] += acc[mt][nt][1] * uA.y + acc[mt][nt][3] * uB.y;
        }
    }
    // reduce over the 8 g-values (lanes with the same tg)
#pragma unroll
    for (int o = 16; o >= 4; o >>= 1) {
#pragma unroll
        for (int nt = 0; nt < NNT; ++nt) {
            pr0[nt] += __shfl_xor_sync(0xffffffffu, pr0[nt], o);
            pr1[nt] += __shfl_xor_sync(0xffffffffu, pr1[nt], o);
        }
    }
    if (lane < 4) {
#pragma unroll
        for (int nt = 0; nt < NNT; ++nt) {
            red[wid][nt * 8 + tg * 2 + 0] = pr0[nt];
            red[wid][nt * 8 + tg * 2 + 1] = pr1[nt];
        }
    }
    __syncthreads();
    if (tid < RR) {
        float s = 0.0f;
#pragma unroll
        for (int w = 0; w < 8; ++w) s += red[w][tid];
        g_t3[b * RR + tid] = s;
    }
}

// ---------------- Kernel 2: out[b,cls] = sum_r t3[b,r]*lam[r]*U4[cls,r] ----------------
__global__ void cp_out(const float* __restrict__ U4, const float* __restrict__ lam,
                       float* __restrict__ out) {
    __shared__ __align__(16) float s[RR];
    int b = blockIdx.y;
    int cls = blockIdx.x * 128 + threadIdx.x;
    if (threadIdx.x < RR) s[threadIdx.x] = g_t3[b * RR + threadIdx.x] * lam[threadIdx.x];
    __syncthreads();
    if (cls < CLS) {
        const float4* u4 = (const float4*)(U4 + (size_t)cls * RR);
        const float4* sv = (const float4*)s;
        float acc = 0.0f;
#pragma unroll
        for (int i = 0; i < 16; ++i) {
            float4 u = u4[i], t = sv[i];
            acc += u.x * t.x + u.y * t.y + u.z * t.z + u.w * t.w;
        }
        out[b * CLS + cls] = acc;
    }
}

// ---------------- launch ----------------
extern "C" void kernel_launch(void* const* d_in, const int* in_sizes, int n_in,
                              void* d_out, int out_size) {
    (void)in_sizes; (void)n_in; (void)out_size;
    const float* x   = (const float*)d_in[0];
    const float* U1  = (const float*)d_in[1];
    const float* U2  = (const float*)d_in[2];
    const float* U3  = (const float*)d_in[3];
    const float* U4  = (const float*)d_in[4];
    const float* lam = (const float*)d_in[5];
    float* out = (float*)d_out;

    cp_prep<<<64, 256>>>(U1, U2);
    cp_main<<<BB, 256>>>(x, U3);
    cp_out<<<dim3((CLS + 127) / 128, BB), 128>>>(U4, lam, out);
}

// round 11
// speedup vs baseline: 1.1955x; 1.1955x over previous
#include <cuda_runtime.h>
#include <cuda_fp16.h>
#include <cstdint>
#include <cstddef>

// Problem dims
#define HH 32
#define WW 32
#define CC 512
#define CLS 1000
#define RR 64
#define BB 128
#define KTOT 1024   // W*H flattened
#define NKT 64      // k16 tiles
#define NNT 8       // n8 tiles (R=64)
#define NMT 4       // m16 tiles per warp (warp M = 64)

#define NSTAGE 4
#define STAGE_FLOATS (CC * 16)          // 8192 floats = 32 KB per stage
#define SMEM_DYN (NSTAGE * STAGE_FLOATS * 4)  // 131072 B

// -------- device scratch (no allocations allowed) --------
// V = U2 (x) U1 per rank, fp16 RN, laid out as m16n8k16 B-fragments
// [kt][lane][nt] (uint2 each). Per lane per kt: 8 uint2 = 4 uint4.
// uint2: .x = half2(V[r][k0],V[r][k0+1]), .y = half2(V[r][k0+8],V[r][k0+9]),
// r = nt*8 + lane/4, k0 = kt*16 + (lane%4)*2.
__device__ uint2 g_Vf[NKT * 32 * NNT];

static __device__ __forceinline__ uint32_t packh2(float a, float b) {
    __half2 h = __floats2half2_rn(a, b);
    return reinterpret_cast<uint32_t&>(h);
}

// ---------------- Kernel 0: precompute V fragments ----------------
__global__ void cp_prep(const float* __restrict__ U1, const float* __restrict__ U2) {
    int gidx = blockIdx.x * 256 + threadIdx.x;   // kt*256 + lane*8 + nt
    int kt = gidx >> 8;
    int lane = (gidx >> 3) & 31;
    int nt = gidx & 7;
    int r  = nt * 8 + (lane >> 2);
    int k0 = kt * 16 + (lane & 3) * 2;

    float v[4];
#pragma unroll
    for (int i = 0; i < 4; ++i) {
        int k = k0 + (i >> 1) * 8 + (i & 1);
        int w = k >> 5, h = k & 31;
        v[i] = U2[w * RR + r] * U1[h * RR + r];
    }
    g_Vf[(kt * 32 + lane) * NNT + nt] =
        make_uint2(packh2(v[0], v[1]), packh2(v[2], v[3]));
}

// ---------------- mma.sync helper ----------------
#define MMA16816(d, a0, a1, a2, a3, b0, b1)                                   \
    asm volatile(                                                             \
        "mma.sync.aligned.m16n8k16.row.col.f32.f16.f16.f32 "                  \
        "{%0,%1,%2,%3}, {%4,%5,%6,%7}, {%8,%9}, {%0,%1,%2,%3};"               \
        : "+f"((d)[0]), "+f"((d)[1]), "+f"((d)[2]), "+f"((d)[3])              \
        : "r"(a0), "r"(a1), "r"(a2), "r"(a3), "r"(b0), "r"(b1))

// ---------------- Kernel 1: fully fused contraction ----------------
// One CTA per batch b. 8 warps x (M=64, N=64), K=1024.
// x staged via 4-deep cp.async pipeline; split-fp16 x (hi+lo) * RN-fp16 V,
// fp32 fragment accumulation. Epilogue: t3[b,r]=sum_c U3[c,r]*s[c,r];
// out[b,cls]=sum_r t3*lam*U4.
__global__ void __launch_bounds__(256, 1)
cp_main(const float* __restrict__ x, const float* __restrict__ U3,
        const float* __restrict__ U4, const float* __restrict__ lam,
        float* __restrict__ out) {
    extern __shared__ float xs[];               // NSTAGE * 8192 floats
    __shared__ float red[8][RR];
    __shared__ __align__(16) float t3s[RR];
    int tid = threadIdx.x, wid = tid >> 5, lane = tid & 31;
    int g = lane >> 2, tg = lane & 3;
    int b = blockIdx.x;

    uint32_t xs_base;
    asm("{ .reg .u64 t; cvta.to.shared.u64 t, %1; cvt.u32.u64 %0, t; }"
        : "=r"(xs_base) : "l"((const void*)xs));

    const char* xg = (const char*)(x + (size_t)b * CC * KTOT);

    // stage s <- k-tile kts: 512 rows x 16 floats, 16B chunks, swizzled c4^(row&3)
    auto issue_stage = [&](int s, int kts) {
        uint32_t sbase = xs_base + (uint32_t)s * (STAGE_FLOATS * 4);
        const char* gp = xg + (size_t)kts * 64;
        int c4 = tid & 3;
        int r0 = tid >> 2;
#pragma unroll
        for (int it = 0; it < 8; ++it) {
            int row = it * 64 + r0;
            const char* src = gp + (size_t)row * (KTOT * 4) + c4 * 16;
            uint32_t dst = sbase + (uint32_t)(row * 64 + ((c4 ^ (row & 3)) * 16));
            asm volatile("cp.async.cg.shared.global [%0], [%1], 16;"
                         :: "r"(dst), "l"(src));
        }
        asm volatile("cp.async.commit_group;" ::: "memory");
    };

    float acc[NMT][NNT][4];
#pragma unroll
    for (int mt = 0; mt < NMT; ++mt)
#pragma unroll
        for (int nt = 0; nt < NNT; ++nt)
#pragma unroll
            for (int i = 0; i < 4; ++i) acc[mt][nt][i] = 0.0f;

    // ---- prologue: fill 4 stages ----
    issue_stage(0, 0);
    issue_stage(1, 1);
    issue_stage(2, 2);
    issue_stage(3, 3);

    // B fragments: [kt][lane][nt] uint2 -> per lane 4 uint4, kt stride 128 uint4
    const uint4* bfp = (const uint4*)g_Vf + lane * 4;
    uint4 br[2][4];
    br[0][0] = bfp[0]; br[0][1] = bfp[1]; br[0][2] = bfp[2]; br[0][3] = bfp[3];

    // A-fragment swizzled column offsets (constant per thread)
    int rem = (tg & 1) * 2;
    int c4a = tg >> 1;          // cols 2tg
    int c4b = 2 + (tg >> 1);    // cols 8+2tg

#pragma unroll 2
    for (int kt = 0; kt < NKT; ++kt) {
        int cur = kt & 1, nxt = cur ^ 1;
        asm volatile("cp.async.wait_group 3;" ::: "memory");
        __syncthreads();   // stage kt&3 ready for all warps

        // prefetch next B fragments (LDG overlapped with MMA chain)
        if (kt + 1 < NKT) {
            const uint4* bp = bfp + (size_t)(kt + 1) * 128;
            br[nxt][0] = bp[0]; br[nxt][1] = bp[1];
            br[nxt][2] = bp[2]; br[nxt][3] = bp[3];
        }

        const uint2* bh = (const uint2*)&br[cur][0];  // 8 fragments
        const float* stg = xs + (size_t)(kt & 3) * STAGE_FLOATS;

#pragma unroll
        for (int mt = 0; mt < NMT; ++mt) {
            int rowl = wid * 64 + mt * 16 + g;
            int sw = rowl & 3;
            const float* st = stg + rowl * 16;
            int oa = (c4a ^ sw) * 4 + rem;
            int ob = (c4b ^ sw) * 4 + rem;
            float2 L0 = *(const float2*)(st + oa);
            float2 L1 = *(const float2*)(st + 128 + oa);   // +8 rows
            float2 L2 = *(const float2*)(st + ob);
            float2 L3 = *(const float2*)(st + 128 + ob);

            // fp32 -> fp16 hi/lo split, packed into A fragments
            float h00 = __half2float(__float2half_rn(L0.x));
            float h01 = __half2float(__float2half_rn(L0.y));
            float h10 = __half2float(__float2half_rn(L1.x));
            float h11 = __half2float(__float2half_rn(L1.y));
            float h20 = __half2float(__float2half_rn(L2.x));
            float h21 = __half2float(__float2half_rn(L2.y));
            float h30 = __half2float(__float2half_rn(L3.x));
            float h31 = __half2float(__float2half_rn(L3.y));

            uint32_t ah0 = packh2(h00, h01);
            uint32_t ah1 = packh2(h10, h11);
            uint32_t ah2 = packh2(h20, h21);
            uint32_t ah3 = packh2(h30, h31);
            uint32_t al0 = packh2(L0.x - h00, L0.y - h01);
            uint32_t al1 = packh2(L1.x - h10, L1.y - h11);
            uint32_t al2 = packh2(L2.x - h20, L2.y - h21);
            uint32_t al3 = packh2(L3.x - h30, L3.y - h31);

#pragma unroll
            for (int nt = 0; nt < NNT; ++nt) {
                MMA16816(acc[mt][nt], ah0, ah1, ah2, ah3, bh[nt].x, bh[nt].y);
                MMA16816(acc[mt][nt], al0, al1, al2, al3, bh[nt].x, bh[nt].y);
            }
        }
        __syncthreads();   // all warps done with stage kt&3
        // refill the just-freed stage (wrapped source keeps group count exact;
        // wrapped data is never consumed)
        issue_stage(kt & 3, (kt + 4) & (NKT - 1));
    }

    // ---- epilogue: weight by U3[c,r], reduce over c ----
    // d0=D[g][r0], d1=D[g][r0+1], d2=D[g+8][r0], d3=D[g+8][r0+1],
    // r0 = nt*8 + tg*2, rows c = wid*64 + mt*16 + {g, g+8}.
    float pr0[NNT], pr1[NNT];
#pragma unroll
    for (int nt = 0; nt < NNT; ++nt) { pr0[nt] = 0.0f; pr1[nt] = 0.0f; }

#pragma unroll
    for (int mt = 0; mt < NMT; ++mt) {
        int crow = wid * 64 + mt * 16 + g;
#pragma unroll
        for (int nt = 0; nt < NNT; ++nt) {
            int r0 = nt * 8 + tg * 2;
            float2 uA = *(const float2*)(U3 + (size_t)crow * RR + r0);
            float2 uB = *(const float2*)(U3 + (size_t)(crow + 8) * RR + r0);
            pr0[nt] += acc[mt][nt][0] * uA.x + acc[mt][nt][2] * uB.x;
            pr1[nt] += acc[mt][nt][1] * uA.y + acc[mt][nt][3] * uB.y;
        }
    }
    // reduce over the 8 g-values (lanes with the same tg)
#pragma unroll
    for (int o = 16; o >= 4; o >>= 1) {
#pragma unroll
        for (int nt = 0; nt < NNT; ++nt) {
            pr0[nt] += __shfl_xor_sync(0xffffffffu, pr0[nt], o);
            pr1[nt] += __shfl_xor_sync(0xffffffffu, pr1[nt], o);
        }
    }
    if (lane < 4) {
#pragma unroll
        for (int nt = 0; nt < NNT; ++nt) {
            red[wid][nt * 8 + tg * 2 + 0] = pr0[nt];
            red[wid][nt * 8 + tg * 2 + 1] = pr1[nt];
        }
    }
    __syncthreads();
    if (tid < RR) {
        float s = 0.0f;
#pragma unroll
        for (int w = 0; w < 8; ++w) s += red[w][tid];
        t3s[tid] = s * lam[tid];
    }
    __syncthreads();

    // ---- fused output: out[b,cls] = sum_r t3s[r] * U4[cls,r] ----
    const float4* sv = (const float4*)t3s;
    float4 tv[16];
#pragma unroll
    for (int i = 0; i < 16; ++i) tv[i] = sv[i];
#pragma unroll
    for (int c4 = 0; c4 < 4; ++c4) {
        int cls = tid + c4 * 256;
        if (cls < CLS) {
            const float4* u4 = (const float4*)(U4 + (size_t)cls * RR);
            float a = 0.0f;
#pragma unroll
            for (int i = 0; i < 16; ++i) {
                float4 u = u4[i], t = tv[i];
                a += u.x * t.x + u.y * t.y + u.z * t.z + u.w * t.w;
            }
            out[b * CLS + cls] = a;
        }
    }
}

// ---------------- launch ----------------
extern "C" void kernel_launch(void* const* d_in, const int* in_sizes, int n_in,
                              void* d_out, int out_size) {
    (void)in_sizes; (void)n_in; (void)out_size;
    const float* x   = (const float*)d_in[0];
    const float* U1  = (const float*)d_in[1];
    const float* U2  = (const float*)d_in[2];
    const float* U3  = (const float*)d_in[3];
    const float* U4  = (const float*)d_in[4];
    const float* lam = (const float*)d_in[5];
    float* out = (float*)d_out;

    cudaFuncSetAttribute(cp_main, cudaFuncAttributeMaxDynamicSharedMemorySize, SMEM_DYN);

    cp_prep<<<64, 256>>>(U1, U2);
    cp_main<<<BB, 256, SMEM_DYN>>>(x, U3, U4, lam, out);
}

// round 12
// speedup vs baseline: 1.3456x; 1.1255x over previous
#include <cuda_runtime.h>
#include <cuda_fp16.h>
#include <cstdint>
#include <cstddef>

// Problem dims
#define HH 32
#define WW 32
#define CC 512
#define CLS 1000
#define RR 64
#define BB 128
#define KTOT 1024   // W*H flattened
#define NKT 64      // k16 tiles
#define NNT 8       // n8 tiles (R=64)
#define NMT 2       // m16 tiles per warp (warp M = 32; 16 warps cover C=512)
#define NWARP 16
#define NTHR 512

#define NSTAGE 4
#define XSTAGE_BYTES (CC * 64)                 // 512 rows x 16 floats = 32 KB
#define BSTAGE_BYTES 2048                      // 32 lanes x 8 uint2
#define B_OFF (NSTAGE * XSTAGE_BYTES)          // 131072
#define SMEM_DYN (B_OFF + NSTAGE * BSTAGE_BYTES)  // 139264 B

// -------- device scratch (no allocations allowed) --------
// V = U2 (x) U1 per rank, fp16 RN, m16n8k16 B-fragments [kt][lane][nt] (uint2).
// uint2: .x = half2(V[r][k0],V[r][k0+1]), .y = half2(V[r][k0+8],V[r][k0+9]),
// r = nt*8 + lane/4, k0 = kt*16 + (lane%4)*2.  Per kt: 2048 B.
__device__ uint2 g_Vf[NKT * 32 * NNT];

static __device__ __forceinline__ uint32_t packh2(float a, float b) {
    __half2 h = __floats2half2_rn(a, b);
    return reinterpret_cast<uint32_t&>(h);
}

// ---------------- Kernel 0: precompute V fragments ----------------
__global__ void cp_prep(const float* __restrict__ U1, const float* __restrict__ U2) {
    int gidx = blockIdx.x * 256 + threadIdx.x;   // kt*256 + lane*8 + nt
    int kt = gidx >> 8;
    int lane = (gidx >> 3) & 31;
    int nt = gidx & 7;
    int r  = nt * 8 + (lane >> 2);
    int k0 = kt * 16 + (lane & 3) * 2;

    float v[4];
#pragma unroll
    for (int i = 0; i < 4; ++i) {
        int k = k0 + (i >> 1) * 8 + (i & 1);
        int w = k >> 5, h = k & 31;
        v[i] = U2[w * RR + r] * U1[h * RR + r];
    }
    g_Vf[(kt * 32 + lane) * NNT + nt] =
        make_uint2(packh2(v[0], v[1]), packh2(v[2], v[3]));
}

// ---------------- mma.sync helper ----------------
#define MMA16816(d, a0, a1, a2, a3, b0, b1)                                   \
    asm volatile(                                                             \
        "mma.sync.aligned.m16n8k16.row.col.f32.f16.f16.f32 "                  \
        "{%0,%1,%2,%3}, {%4,%5,%6,%7}, {%8,%9}, {%0,%1,%2,%3};"               \
        : "+f"((d)[0]), "+f"((d)[1]), "+f"((d)[2]), "+f"((d)[3])              \
        : "r"(a0), "r"(a1), "r"(a2), "r"(a3), "r"(b0), "r"(b1))

// ---------------- Kernel 1: fully fused contraction ----------------
// One CTA per batch b. 16 warps x (M=32, N=64), K=1024.
// x and B staged via 4-deep cp.async pipeline; split-fp16 x (hi+lo) * RN-fp16 V,
// fp32 fragment accumulation. Epilogue fused through to out[b,cls].
__global__ void __launch_bounds__(NTHR, 1)
cp_main(const float* __restrict__ x, const float* __restrict__ U3,
        const float* __restrict__ U4, const float* __restrict__ lam,
        float* __restrict__ out) {
    extern __shared__ float xs[];               // dynamic: x stages + B stages
    __shared__ float red[NWARP][RR];
    __shared__ __align__(16) float t3s[RR];
    int tid = threadIdx.x, wid = tid >> 5, lane = tid & 31;
    int g = lane >> 2, tg = lane & 3;
    int b = blockIdx.x;

    uint32_t xs_base;
    asm("{ .reg .u64 t; cvta.to.shared.u64 t, %1; cvt.u32.u64 %0, t; }"
        : "=r"(xs_base) : "l"((const void*)xs));

    const char* xg = (const char*)(x + (size_t)b * CC * KTOT);
    const char* bg = (const char*)g_Vf;

    // stage s <- k-tile kts:
    //  x: 512 rows x 16 floats, 16B chunks, swizzle c4^(row&3)
    //  B: 2 KB, interleaved [q][lane] (dst q*512+l*16 <- src l*64+q*16)
    auto issue_stage = [&](int s, int kts) {
        uint32_t sxb = xs_base + (uint32_t)s * XSTAGE_BYTES;
        const char* gp = xg + (size_t)kts * 64;
        int c4 = tid & 3;
        int r0 = tid >> 2;          // 0..127
#pragma unroll
        for (int it = 0; it < 4; ++it) {
            int row = it * 128 + r0;
            const char* src = gp + (size_t)row * (KTOT * 4) + c4 * 16;
            uint32_t dst = sxb + (uint32_t)(row * 64 + ((c4 ^ (row & 3)) * 16));
            asm volatile("cp.async.cg.shared.global [%0], [%1], 16;"
                         :: "r"(dst), "l"(src));
        }
        if (tid < 128) {
            int l = tid & 31, q = tid >> 5;
            const char* src = bg + (size_t)kts * 2048 + l * 64 + q * 16;
            uint32_t dst = xs_base + B_OFF + (uint32_t)s * BSTAGE_BYTES
                         + (uint32_t)(q * 512 + l * 16);
            asm volatile("cp.async.cg.shared.global [%0], [%1], 16;"
                         :: "r"(dst), "l"(src));
        }
        asm volatile("cp.async.commit_group;" ::: "memory");
    };

    float acc[NMT][NNT][4];
#pragma unroll
    for (int mt = 0; mt < NMT; ++mt)
#pragma unroll
        for (int nt = 0; nt < NNT; ++nt)
#pragma unroll
            for (int i = 0; i < 4; ++i) acc[mt][nt][i] = 0.0f;

    // ---- prologue: fill 4 stages ----
    issue_stage(0, 0);
    issue_stage(1, 1);
    issue_stage(2, 2);
    issue_stage(3, 3);

    // A-fragment swizzled column offsets (constant per thread)
    int rem = (tg & 1) * 2;
    int c4a = tg >> 1;          // cols 2tg
    int c4b = 2 + (tg >> 1);    // cols 8+2tg

#pragma unroll 2
    for (int kt = 0; kt < NKT; ++kt) {
        asm volatile("cp.async.wait_group 3;" ::: "memory");
        __syncthreads();   // stage kt&3 ready for all warps

        int s = kt & 3;
        const float* stg = xs + (size_t)s * (XSTAGE_BYTES / 4);

        // B fragments from smem (conflict-free: lane reads q*512 + lane*16)
        uint4 brq[4];
        uint32_t bsb = xs_base + B_OFF + (uint32_t)s * BSTAGE_BYTES + lane * 16;
#pragma unroll
        for (int q = 0; q < 4; ++q) {
            asm volatile("ld.shared.v4.b32 {%0,%1,%2,%3}, [%4];"
                         : "=r"(brq[q].x), "=r"(brq[q].y), "=r"(brq[q].z), "=r"(brq[q].w)
                         : "r"(bsb + q * 512));
        }
        const uint2* bh = (const uint2*)&brq[0];  // 8 fragments

#pragma unroll
        for (int mt = 0; mt < NMT; ++mt) {
            int rowl = wid * 32 + mt * 16 + g;
            int sw = rowl & 3;
            const float* st = stg + rowl * 16;
            int oa = (c4a ^ sw) * 4 + rem;
            int ob = (c4b ^ sw) * 4 + rem;
            float2 L0 = *(const float2*)(st + oa);
            float2 L1 = *(const float2*)(st + 128 + oa);   // +8 rows
            float2 L2 = *(const float2*)(st + ob);
            float2 L3 = *(const float2*)(st + 128 + ob);

            // fp32 -> fp16 hi/lo split, packed into A fragments
            float h00 = __half2float(__float2half_rn(L0.x));
            float h01 = __half2float(__float2half_rn(L0.y));
            float h10 = __half2float(__float2half_rn(L1.x));
            float h11 = __half2float(__float2half_rn(L1.y));
            float h20 = __half2float(__float2half_rn(L2.x));
            float h21 = __half2float(__float2half_rn(L2.y));
            float h30 = __half2float(__float2half_rn(L3.x));
            float h31 = __half2float(__float2half_rn(L3.y));

            uint32_t ah0 = packh2(h00, h01);
            uint32_t ah1 = packh2(h10, h11);
            uint32_t ah2 = packh2(h20, h21);
            uint32_t ah3 = packh2(h30, h31);
            uint32_t al0 = packh2(L0.x - h00, L0.y - h01);
            uint32_t al1 = packh2(L1.x - h10, L1.y - h11);
            uint32_t al2 = packh2(L2.x - h20, L2.y - h21);
            uint32_t al3 = packh2(L3.x - h30, L3.y - h31);

#pragma unroll
            for (int nt = 0; nt < NNT; ++nt) {
                MMA16816(acc[mt][nt], ah0, ah1, ah2, ah3, bh[nt].x, bh[nt].y);
                MMA16816(acc[mt][nt], al0, al1, al2, al3, bh[nt].x, bh[nt].y);
            }
        }
        __syncthreads();   // all warps done with stage kt&3
        // refill freed stage (wrapped source keeps group count exact; wrapped
        // data never consumed)
        issue_stage(s, (kt + 4) & (NKT - 1));
    }

    // ---- epilogue: weight by U3[c,r], reduce over c ----
    // d0=D[g][r0], d1=D[g][r0+1], d2=D[g+8][r0], d3=D[g+8][r0+1],
    // r0 = nt*8 + tg*2, rows c = wid*32 + mt*16 + {g, g+8}.
    float pr0[NNT], pr1[NNT];
#pragma unroll
    for (int nt = 0; nt < NNT; ++nt) { pr0[nt] = 0.0f; pr1[nt] = 0.0f; }

#pragma unroll
    for (int mt = 0; mt < NMT; ++mt) {
        int crow = wid * 32 + mt * 16 + g;
#pragma unroll
        for (int nt = 0; nt < NNT; ++nt) {
            int r0 = nt * 8 + tg * 2;
            float2 uA = *(const float2*)(U3 + (size_t)crow * RR + r0);
            float2 uB = *(const float2*)(U3 + (size_t)(crow + 8) * RR + r0);
            pr0[nt] += acc[mt][nt][0] * uA.x + acc[mt][nt][2] * uB.x;
            pr1[nt] += acc[mt][nt][1] * uA.y + acc[mt][nt][3] * uB.y;
        }
    }
    // reduce over the 8 g-values (lanes with same tg)
#pragma unroll
    for (int o = 16; o >= 4; o >>= 1) {
#pragma unroll
        for (int nt = 0; nt < NNT; ++nt) {
            pr0[nt] += __shfl_xor_sync(0xffffffffu, pr0[nt], o);
            pr1[nt] += __shfl_xor_sync(0xffffffffu, pr1[nt], o);
        }
    }
    if (lane < 4) {
#pragma unroll
        for (int nt = 0; nt < NNT; ++nt) {
            red[wid][nt * 8 + tg * 2 + 0] = pr0[nt];
            red[wid][nt * 8 + tg * 2 + 1] = pr1[nt];
        }
    }
    __syncthreads();
    if (tid < RR) {
        float s = 0.0f;
#pragma unroll
        for (int w = 0; w < NWARP; ++w) s += red[w][tid];
        t3s[tid] = s * lam[tid];
    }
    __syncthreads();

    // ---- fused output: out[b,cls] = sum_r t3s[r] * U4[cls,r] ----
    const float4* sv = (const float4*)t3s;
    float4 tv[16];
#pragma unroll
    for (int i = 0; i < 16; ++i) tv[i] = sv[i];
#pragma unroll
    for (int c2 = 0; c2 < 2; ++c2) {
        int cls = tid + c2 * NTHR;
        if (cls < CLS) {
            const float4* u4 = (const float4*)(U4 + (size_t)cls * RR);
            float a = 0.0f;
#pragma unroll
            for (int i = 0; i < 16; ++i) {
                float4 u = u4[i], t = tv[i];
                a += u.x * t.x + u.y * t.y + u.z * t.z + u.w * t.w;
            }
            out[b * CLS + cls] = a;
        }
    }
}

// ---------------- launch ----------------
extern "C" void kernel_launch(void* const* d_in, const int* in_sizes, int n_in,
                              void* d_out, int out_size) {
    (void)in_sizes; (void)n_in; (void)out_size;
    const float* x   = (const float*)d_in[0];
    const float* U1  = (const float*)d_in[1];
    const float* U2  = (const float*)d_in[2];
    const float* U3  = (const float*)d_in[3];
    const float* U4  = (const float*)d_in[4];
    const float* lam = (const float*)d_in[5];
    float* out = (float*)d_out;

    cudaFuncSetAttribute(cp_main, cudaFuncAttributeMaxDynamicSharedMemorySize, SMEM_DYN);

    cp_prep<<<64, 256>>>(U1, U2);
    cp_main<<<BB, NTHR, SMEM_DYN>>>(x, U3, U4, lam, out);
}